// round 15
// baseline (speedup 1.0000x reference)
#include <cuda_runtime.h>
#include <cuda_fp16.h>
#include <math.h>

#define N_B    2
#define C_DIM  512
#define S_TOT  13294
#define FL_N   4

// Level geometry (H, W, flat offset in s)
__constant__ int c_H[4]   = {100, 50, 25, 13};
__constant__ int c_W[4]   = {100, 50, 25, 13};
__constant__ int c_off[4] = {0, 10000, 12500, 13125};

// ---------------- device scratch ----------------
__device__ __align__(16) __half g_value[N_B * S_TOT * C_DIM];   // fp16, (n,s,c)
__device__ __align__(16) float  g_offw[N_B * S_TOT * 128];      // fp32 logits per query
__device__ __align__(16) __half g_xT_hi[N_B * S_TOT * C_DIM];   // x^T (n,s,k) fp16 split
__device__ __align__(16) __half g_xT_lo[N_B * S_TOT * C_DIM];
__device__ __align__(16) __half g_xpT_hi[N_B * S_TOT * C_DIM];  // (x+pos)^T fp16 split
__device__ __align__(16) __half g_xpT_lo[N_B * S_TOT * C_DIM];
__device__ __align__(16) __half g_pre_hi[N_B * S_TOT * C_DIM];  // sampled (n,s,c) fp16 split
__device__ __align__(16) __half g_pre_lo[N_B * S_TOT * C_DIM];
__device__ __align__(16) __half g_Wv[C_DIM * C_DIM];            // plain fp16 weights
__device__ __align__(16) __half g_Wo[C_DIM * C_DIM];
__device__ __align__(16) __half g_Wc[128 * C_DIM];              // [Wloc;Ww;0] padded
__device__ __align__(16) float  g_bcat[128];                    // [bloc;bw;0]

// ---------------- PTX helpers (arch-generic, no 103a features) ----------------
__device__ __forceinline__ unsigned smem_u32(const void* p) {
    unsigned a;
    asm("{ .reg .u64 t; cvta.to.shared.u64 t, %1; cvt.u32.u64 %0, t; }" : "=r"(a) : "l"(p));
    return a;
}
__device__ __forceinline__ void cp16(unsigned dst, const void* src, int ok) {
    int sz = ok ? 16 : 0;
    asm volatile("cp.async.cg.shared.global [%0], [%1], 16, %2;"
                 :: "r"(dst), "l"(src), "r"(sz) : "memory");
}
#define CP_COMMIT() asm volatile("cp.async.commit_group;" ::: "memory")
#define CP_WAIT(n)  asm volatile("cp.async.wait_group %0;" :: "n"(n) : "memory")

#define LDSM4(r, addr) \
    asm volatile("ldmatrix.sync.aligned.m8n8.x4.shared.b16 {%0,%1,%2,%3}, [%4];" \
                 : "=r"((r)[0]), "=r"((r)[1]), "=r"((r)[2]), "=r"((r)[3]) : "r"(addr))

__device__ __forceinline__ void mma_f16(float* d, const unsigned* a, const unsigned* b) {
    asm volatile(
        "mma.sync.aligned.m16n8k16.row.col.f32.f16.f16.f32 "
        "{%0,%1,%2,%3}, {%4,%5,%6,%7}, {%8,%9}, {%0,%1,%2,%3};"
        : "+f"(d[0]), "+f"(d[1]), "+f"(d[2]), "+f"(d[3])
        : "r"(a[0]), "r"(a[1]), "r"(a[2]), "r"(a[3]), "r"(b[0]), "r"(b[1]));
}

// smem geometry: padded rows (32 halves + 8 pad = 80 B) -> conflict-free ldmatrix
#define KC          32
#define ROW_B       80
#define BUF_B       (128 * ROW_B)      // 10240
#define STAGE_B     (3 * BUF_B)        // 30720  (SplitHi, SplitLo, Plain)
#define NSTAGE      3
#define GEMM_SMEM   (NSTAGE * STAGE_B) // 92160
#define NCHUNK      (C_DIM / KC)       // 16

// =====================================================================
// prep: fp32 -> plain fp16 (Wv at y=0, Wo at y=1)
// =====================================================================
__global__ void k_cvt(const float* __restrict__ Wv, const float* __restrict__ Wo) {
    int i = blockIdx.x * 256 + threadIdx.x;
    const float* src = blockIdx.y ? Wo : Wv;
    __half* dst = blockIdx.y ? g_Wo : g_Wv;
    dst[i] = __float2half_rn(src[i]);
}

// =====================================================================
// prep: [Wloc(64);Ww(32);0(32)] -> g_Wc plain fp16 (128x512), g_bcat
// =====================================================================
__global__ void k_prep_w(const float* __restrict__ Wloc, const float* __restrict__ bloc,
                         const float* __restrict__ Ww,   const float* __restrict__ bw) {
    int r = blockIdx.x, c = threadIdx.x;
    float v = (r < 64) ? Wloc[(size_t)r * C_DIM + c]
            : (r < 96) ? Ww[(size_t)(r - 64) * C_DIM + c] : 0.0f;
    g_Wc[(size_t)r * C_DIM + c] = __float2half_rn(v);
    if (c == 0)
        g_bcat[r] = (r < 64) ? bloc[r] : (r < 96) ? bw[r - 64] : 0.0f;
}

// =====================================================================
// prep: x,pos [n][k][s] fp32 -> xT and (x+pos)T fp16 hi/lo (32x32 transpose)
// =====================================================================
__global__ void k_convX(const float* __restrict__ x, const float* __restrict__ pos,
                        const unsigned char* __restrict__ mask) {
    __shared__ float tx[32][33], tp[32][33];
    const int s0 = blockIdx.x * 32, k0 = blockIdx.y * 32, n = blockIdx.z;
    const int txi = threadIdx.x, tyi = threadIdx.y;
#pragma unroll
    for (int r = 0; r < 4; r++) {
        int k = k0 + tyi + r * 8, s = s0 + txi;
        size_t gi = ((size_t)n * C_DIM + k) * S_TOT + s;
        tx[tyi + r * 8][txi] = (s < S_TOT) ? x[gi] : 0.0f;
        tp[tyi + r * 8][txi] = (s < S_TOT) ? pos[gi] : 0.0f;
    }
    __syncthreads();
#pragma unroll
    for (int r = 0; r < 4; r++) {
        int s = s0 + tyi + r * 8, k = k0 + txi;
        if (s < S_TOT) {
            float xv = tx[txi][tyi + r * 8];
            float pv = tp[txi][tyi + r * 8];
            bool m = mask[(size_t)n * S_TOT + s] != 0;
            size_t o = ((size_t)n * S_TOT + s) * C_DIM + k;
            __half h = __float2half_rn(xv);
            g_xT_hi[o] = h;
            g_xT_lo[o] = __float2half_rn(xv - __half2float(h));
            float xp = m ? 0.0f : (xv + pv);
            __half hp = __float2half_rn(xp);
            g_xpT_hi[o] = hp;
            g_xpT_lo[o] = __float2half_rn(xp - __half2float(hp));
        }
    }
}

// =====================================================================
// HMMA GEMM, fp16 2-term: activation split (hi+lo, exact), weight plain fp16.
// 3-stage cp.async pipeline, ONE __syncthreads per chunk.
// MODE 0: D[s][c] = xT @ Wv^T   -> g_value fp16 (+bv, mask)
// MODE 1: D[c][s] = Wo @ pre^T  -> out (scale*(v+bo))
// MODE 2: D[s][r] = xpT @ Wc^T  -> g_offw (+bcat)
// Block tile 128(m) x 128(n); 128 threads = 4 warps of 64(m) x 64(n).
// =====================================================================
template<int MODE>
__global__ void __launch_bounds__(128, 2) k_gemm(
    const unsigned char* __restrict__ mask,
    const float* __restrict__ bias,
    const float* __restrict__ scl,
    float* __restrict__ outp)
{
    extern __shared__ char smem[];
    const int t = threadIdx.x, lane = t & 31, wid = t >> 5;
    const int mb = blockIdx.x * 128;
    const int nb = blockIdx.y * 128;
    const int n  = blockIdx.z;
    const unsigned sbase = smem_u32(smem);

    // X = split operand (hi/lo), Y = plain operand
    const __half *Xh, *Xl, *Yp;
    int x_row0, x_lim, y_row0, y_lim;
    if (MODE == 0) {
        Xh = g_xT_hi + (size_t)n * S_TOT * C_DIM;
        Xl = g_xT_lo + (size_t)n * S_TOT * C_DIM;
        x_row0 = mb; x_lim = S_TOT;
        Yp = g_Wv; y_row0 = nb; y_lim = C_DIM;
    } else if (MODE == 1) {
        Xh = g_pre_hi + (size_t)n * S_TOT * C_DIM;
        Xl = g_pre_lo + (size_t)n * S_TOT * C_DIM;
        x_row0 = nb; x_lim = S_TOT;
        Yp = g_Wo; y_row0 = mb; y_lim = C_DIM;
    } else {
        Xh = g_xpT_hi + (size_t)n * S_TOT * C_DIM;
        Xl = g_xpT_lo + (size_t)n * S_TOT * C_DIM;
        x_row0 = mb; x_lim = S_TOT;
        Yp = g_Wc; y_row0 = nb; y_lim = 128;
    }

    // loader (128 threads): row = t>>2 (+32*i), seg = t&3 (4 x 16B = 64B/row)
    const int l_row0 = t >> 2, l_seg = t & 3;
#define ISSUE(chunk)                                                                   \
    {                                                                                  \
        const int k0 = (chunk) * KC;                                                   \
        const unsigned st_ = sbase + ((chunk) % NSTAGE) * STAGE_B;                     \
        _Pragma("unroll")                                                              \
        for (int i_ = 0; i_ < 4; i_++) {                                               \
            int row = l_row0 + i_ * 32;                                                \
            unsigned doff = row * ROW_B + l_seg * 16;                                  \
            int rx = x_row0 + row; int okx = rx < x_lim; rx = okx ? rx : 0;            \
            size_t gx = (size_t)rx * C_DIM + k0 + l_seg * 8;                           \
            cp16(st_ + 0 * BUF_B + doff, Xh + gx, okx);                                \
            cp16(st_ + 1 * BUF_B + doff, Xl + gx, okx);                                \
            int ry = y_row0 + row; int oky = ry < y_lim; ry = oky ? ry : 0;            \
            size_t gy = (size_t)ry * C_DIM + k0 + l_seg * 8;                           \
            cp16(st_ + 2 * BUF_B + doff, Yp + gy, oky);                                \
        }                                                                              \
        CP_COMMIT();                                                                   \
    }

    const int wm = (wid >> 1) * 64;   // 2 warp rows (m)
    const int wn = (wid & 1) * 64;    // 2 warp cols (n)
    const unsigned aoff = (wm + (lane & 15)) * ROW_B + ((lane & 16) ? 16 : 0);
    const unsigned boff = (wn + (lane & 7) + ((lane & 16) ? 8 : 0)) * ROW_B
                        + ((lane & 8) ? 16 : 0);

    float acc[4][8][4];
#pragma unroll
    for (int a = 0; a < 4; a++)
#pragma unroll
        for (int b = 0; b < 8; b++)
#pragma unroll
            for (int j = 0; j < 4; j++) acc[a][b][j] = 0.0f;

    ISSUE(0);
    ISSUE(1);
    for (int c = 0; c < NCHUNK; c++) {
        if (c == NCHUNK - 1) { CP_WAIT(0); }
        else                 { CP_WAIT(1); }
        __syncthreads();   // chunk c arrived AND compute(c-1) drained in all warps
        if (c + 2 < NCHUNK) ISSUE(c + 2);   // overwrites stage (c-1)%3 — safe post-sync
        const unsigned st = sbase + (c % NSTAGE) * STAGE_B;
#pragma unroll
        for (int ks = 0; ks < 2; ks++) {
            if (MODE == 1) {
                // A plain (Wo), B split (pre)
                unsigned a4[4][4];
#pragma unroll
                for (int mt = 0; mt < 4; mt++)
                    LDSM4(a4[mt], st + 2 * BUF_B + aoff + mt * (16 * ROW_B) + ks * 32);
#pragma unroll
                for (int g = 0; g < 4; g++) {
                    unsigned bh[4], bl[4];
                    LDSM4(bh, st + 0 * BUF_B + boff + g * (16 * ROW_B) + ks * 32);
                    LDSM4(bl, st + 1 * BUF_B + boff + g * (16 * ROW_B) + ks * 32);
#pragma unroll
                    for (int j = 0; j < 2; j++) {
#pragma unroll
                        for (int mt = 0; mt < 4; mt++) {
                            float* d = acc[mt][g * 2 + j];
                            mma_f16(d, a4[mt], &bh[2 * j]);
                            mma_f16(d, a4[mt], &bl[2 * j]);
                        }
                    }
                }
            } else {
                // A split (xT/xpT), B plain (Wv/Wc)
                unsigned ahi[4][4], alo[4][4];
#pragma unroll
                for (int mt = 0; mt < 4; mt++) {
                    LDSM4(ahi[mt], st + 0 * BUF_B + aoff + mt * (16 * ROW_B) + ks * 32);
                    LDSM4(alo[mt], st + 1 * BUF_B + aoff + mt * (16 * ROW_B) + ks * 32);
                }
#pragma unroll
                for (int g = 0; g < 4; g++) {
                    unsigned b4[4];
                    LDSM4(b4, st + 2 * BUF_B + boff + g * (16 * ROW_B) + ks * 32);
#pragma unroll
                    for (int j = 0; j < 2; j++) {
#pragma unroll
                        for (int mt = 0; mt < 4; mt++) {
                            float* d = acc[mt][g * 2 + j];
                            mma_f16(d, ahi[mt], &b4[2 * j]);
                            mma_f16(d, alo[mt], &b4[2 * j]);
                        }
                    }
                }
            }
        }
    }
#undef ISSUE

    // ---- epilogue: n-dim is the contiguous store dim in all modes ----
    if (MODE == 0) {
        const unsigned char* mk = mask + (size_t)n * S_TOT;
        __half* dst = g_value + (size_t)n * S_TOT * C_DIM;
#pragma unroll
        for (int mt = 0; mt < 4; mt++) {
            int s0 = mb + wm + mt * 16 + (lane >> 2);
#pragma unroll
            for (int tn = 0; tn < 8; tn++) {
                int cc = nb + wn + tn * 8 + 2 * (lane & 3);
                float2 bp = *(const float2*)(bias + cc);
                float* d = acc[mt][tn];
                if (s0 < S_TOT) {
                    float m = mk[s0] ? 0.0f : 1.0f;
                    __half2 h = __floats2half2_rn(m * (d[0] + bp.x), m * (d[1] + bp.y));
                    *(__half2*)(dst + (size_t)s0 * C_DIM + cc) = h;
                }
                int s1 = s0 + 8;
                if (s1 < S_TOT) {
                    float m = mk[s1] ? 0.0f : 1.0f;
                    __half2 h = __floats2half2_rn(m * (d[2] + bp.x), m * (d[3] + bp.y));
                    *(__half2*)(dst + (size_t)s1 * C_DIM + cc) = h;
                }
            }
        }
    } else if (MODE == 1) {
#pragma unroll
        for (int mt = 0; mt < 4; mt++) {
            int c0 = mb + wm + mt * 16 + (lane >> 2);
            int c1 = c0 + 8;
            float sc0 = scl[c0], b0 = bias[c0];
            float sc1 = scl[c1], b1 = bias[c1];
            float* r0 = outp + ((size_t)n * C_DIM + c0) * S_TOT;
            float* r1 = outp + ((size_t)n * C_DIM + c1) * S_TOT;
#pragma unroll
            for (int tn = 0; tn < 8; tn++) {
                int ss = nb + wn + tn * 8 + 2 * (lane & 3);
                float* d = acc[mt][tn];
                if (ss < S_TOT) {   // S_TOT even, ss even -> pair fully in-bounds
                    float2 v0; v0.x = sc0 * (d[0] + b0); v0.y = sc0 * (d[1] + b0);
                    *(float2*)(r0 + ss) = v0;
                    float2 v1; v1.x = sc1 * (d[2] + b1); v1.y = sc1 * (d[3] + b1);
                    *(float2*)(r1 + ss) = v1;
                }
            }
        }
    } else {
        float* dst = g_offw + (size_t)n * S_TOT * 128;
#pragma unroll
        for (int mt = 0; mt < 4; mt++) {
            int s0 = mb + wm + mt * 16 + (lane >> 2);
#pragma unroll
            for (int tn = 0; tn < 8; tn++) {
                int cc = wn + tn * 8 + 2 * (lane & 3);
                float2 bp = *(const float2*)(bias + cc);
                float* d = acc[mt][tn];
                if (s0 < S_TOT) {
                    float2 v; v.x = d[0] + bp.x; v.y = d[1] + bp.y;
                    *(float2*)(dst + (size_t)s0 * 128 + cc) = v;
                }
                int s1 = s0 + 8;
                if (s1 < S_TOT) {
                    float2 v; v.x = d[2] + bp.x; v.y = d[3] + bp.y;
                    *(float2*)(dst + (size_t)s1 * 128 + cc) = v;
                }
            }
        }
    }
}

// =====================================================================
// k_gather: read logits from g_offw, softmax over levels, bilinear-sample
// g_value (fp16), weighted sum -> g_pre_hi/lo (fp16 split). Warp per query.
// =====================================================================
__global__ void __launch_bounds__(256) k_gather(
    const float* __restrict__ vsz, const float* __restrict__ vsc)
{
    const int lvl = blockIdx.y, n = blockIdx.z;
    const int H = c_H[lvl], W = c_W[lvl];
    const int L = H * W, loff = c_off[lvl];
    const int wid = threadIdx.x >> 5, lane = threadIdx.x & 31;
    const int gq = blockIdx.x * 8 + wid;
    if (gq >= L) return;

    const float scx = 2.0f * vsc[((size_t)n * FL_N + lvl) * 2 + 0] / vsz[((size_t)n * FL_N + lvl) * 2 + 0];
    const float scy = 2.0f * vsc[((size_t)n * FL_N + lvl) * 2 + 1] / vsz[((size_t)n * FL_N + lvl) * 2 + 1];

    int row = gq / W, col = gq - row * W;
    float prex = col + 0.5f, prey = row + 0.5f;
    int s_q = loff + gq;

    const float* ow = g_offw + (size_t)(n * S_TOT + s_q) * 128;
    float v0 = ow[lane], v1 = ow[32 + lane], v2 = ow[64 + lane];

    for (int m = 0; m < 8; m++) {
        float vo = (m < 4) ? v0 : v1;
        float l0 = __shfl_sync(0xFFFFFFFFu, v2, m * 4 + 0);
        float l1 = __shfl_sync(0xFFFFFFFFu, v2, m * 4 + 1);
        float l2 = __shfl_sync(0xFFFFFFFFu, v2, m * 4 + 2);
        float l3 = __shfl_sync(0xFFFFFFFFu, v2, m * 4 + 3);
        float mx = fmaxf(fmaxf(l0, l1), fmaxf(l2, l3));
        float e0 = __expf(l0 - mx), e1 = __expf(l1 - mx);
        float e2 = __expf(l2 - mx), e3 = __expf(l3 - mx);
        float inv = 1.0f / (e0 + e1 + e2 + e3);
        float wgt[4] = {e0 * inv, e1 * inv, e2 * inv, e3 * inv};

        float a0 = 0.0f, a1 = 0.0f;
#pragma unroll
        for (int f = 0; f < 4; f++) {
            int Hf = c_H[f], Wf = c_W[f], lof = c_off[f];
            int rbase = (m * 8 + f * 2) & 31;
            float offx = __shfl_sync(0xFFFFFFFFu, vo, rbase);
            float offy = __shfl_sync(0xFFFFFFFFu, vo, rbase + 1);
            float xx = (offx + prex) * (scx * 0.5f * (float)Wf) - 0.5f;
            float yy = (offy + prey) * (scy * 0.5f * (float)Hf) - 0.5f;
            float x0f = floorf(xx), y0f = floorf(yy);
            int ix0 = (int)x0f, iy0 = (int)y0f;
            float wx1 = xx - x0f, wy1 = yy - y0f;
            float wx0 = 1.0f - wx1, wy0 = 1.0f - wy1;
            float wf = wgt[f];
            const __half* vb = g_value + ((size_t)n * S_TOT + lof) * C_DIM + m * 64 + lane * 2;
#define CORNER(ix, iy, cw) \
            if ((unsigned)(ix) < (unsigned)Wf && (unsigned)(iy) < (unsigned)Hf) { \
                __half2 v = *(const __half2*)(vb + ((size_t)(iy) * Wf + (ix)) * C_DIM); \
                float2 vf = __half22float2(v); \
                float w_ = wf * (cw); a0 += w_ * vf.x; a1 += w_ * vf.y; }
            CORNER(ix0,     iy0,     wx0 * wy0)
            CORNER(ix0 + 1, iy0,     wx1 * wy0)
            CORNER(ix0,     iy0 + 1, wx0 * wy1)
            CORNER(ix0 + 1, iy0 + 1, wx1 * wy1)
#undef CORNER
        }
        __half2 hv, lv;
        hv.x = __float2half_rn(a0);
        lv.x = __float2half_rn(a0 - __half2float(hv.x));
        hv.y = __float2half_rn(a1);
        lv.y = __float2half_rn(a1 - __half2float(hv.y));
        size_t oi = (size_t)(n * S_TOT + s_q) * (C_DIM / 2) + m * 32 + lane;
        ((__half2*)g_pre_hi)[oi] = hv;
        ((__half2*)g_pre_lo)[oi] = lv;
    }
}

extern "C" void kernel_launch(void* const* d_in, const int* in_sizes, int n_in,
                              void* d_out, int out_size) {
    const float* x    = (const float*)d_in[0];
    const float* pos  = (const float*)d_in[1];
    const unsigned char* mask = (const unsigned char*)d_in[2];
    const float* vsz  = (const float*)d_in[3];
    const float* vsc  = (const float*)d_in[4];
    const float* Wv   = (const float*)d_in[5];
    const float* bv   = (const float*)d_in[6];
    const float* Wloc = (const float*)d_in[7];
    const float* bloc = (const float*)d_in[8];
    const float* Ww   = (const float*)d_in[9];
    const float* bw   = (const float*)d_in[10];
    const float* Wo   = (const float*)d_in[11];
    const float* bo   = (const float*)d_in[12];
    const float* scale = (const float*)d_in[13];
    float* out = (float*)d_out;

    cudaFuncSetAttribute(k_gemm<0>, cudaFuncAttributeMaxDynamicSharedMemorySize, GEMM_SMEM);
    cudaFuncSetAttribute(k_gemm<1>, cudaFuncAttributeMaxDynamicSharedMemorySize, GEMM_SMEM);
    cudaFuncSetAttribute(k_gemm<2>, cudaFuncAttributeMaxDynamicSharedMemorySize, GEMM_SMEM);

    void* p_bcat;
    cudaGetSymbolAddress(&p_bcat, g_bcat);

    // prep: convert weights, build concat proj weights, transpose+split x / x+pos
    k_cvt<<<dim3(1024, 2), 256>>>(Wv, Wo);
    k_prep_w<<<128, 512>>>(Wloc, bloc, Ww, bw);
    k_convX<<<dim3((S_TOT + 31) / 32, C_DIM / 32, N_B), dim3(32, 8)>>>(x, pos, mask);

    // value GEMM: D[s][c] -> fp16 g_value
    k_gemm<0><<<dim3((S_TOT + 127) / 128, C_DIM / 128, N_B), 128, GEMM_SMEM>>>(
        mask, bv, nullptr, nullptr);

    // offset/weight logits GEMM: D[s][r], N = 128
    k_gemm<2><<<dim3((S_TOT + 127) / 128, 1, N_B), 128, GEMM_SMEM>>>(
        mask, (const float*)p_bcat, nullptr, nullptr);

    // deformable sampling (gather-only)
    k_gather<<<dim3(1250, FL_N, N_B), 256>>>(vsz, vsc);

    // output GEMM: D[c][s]
    k_gemm<1><<<dim3(C_DIM / 128, (S_TOT + 127) / 128, N_B), 128, GEMM_SMEM>>>(
        mask, bo, scale, out);
}